// round 6
// baseline (speedup 1.0000x reference)
#include <cuda_runtime.h>
#include <math.h>

typedef unsigned long long ull;

#define BSZ 8
#define CIN 64
#define MID 32
#define HH 256
#define WW 256
#define TS 16
#define PS 18
#define PP 324
#define BN_EPS 1e-5f
#define NWARP 16

// ---------------- f32x2 helpers ----------------
#define FMA2(a, x, w) asm("fma.rn.f32x2 %0, %1, %2, %0;" : "+l"(a) : "l"(x), "l"(w))
__device__ __forceinline__ ull pk2(float x) {
    ull d; unsigned u = __float_as_uint(x);
    asm("mov.b64 %0, {%1, %1};" : "=l"(d) : "r"(u)); return d;
}
__device__ __forceinline__ void upk(ull v, float& lo, float& hi) {
    unsigned a, b;
    asm("mov.b64 {%0, %1}, %2;" : "=r"(a), "=r"(b) : "l"(v));
    lo = __uint_as_float(a); hi = __uint_as_float(b);
}
// (hi of a, lo of b)
__device__ __forceinline__ ull mid2(ull a, ull b) {
    ull r;
    asm("{\n\t.reg .b32 xl, xh, yl, yh;\n\t"
        "mov.b64 {xl, xh}, %1;\n\t"
        "mov.b64 {yl, yh}, %2;\n\t"
        "mov.b64 %0, {xh, yl};\n\t}"
        : "=l"(r) : "l"(a), "l"(b));
    return r;
}

// ---------------- selection / schedule metadata ----------------
__device__ float g_scale[64];
__device__ int   g_slot[64];
__device__ int   g_list3[40];

#define MAXIT 80
__device__ int g_it_kind[MAXIT];   // 0 br0-pair, 1 br1-pair, 2 br2-pair, 3 avg-single, 4 t1-prep, 5 ta-prep
__device__ int g_it_a[MAXIT];
__device__ int g_it_b[MAXIT];
__device__ int g_it_c0[MAXIT];
__device__ int g_it_c1[MAXIT];
__device__ int g_it_off[MAXIT];

__device__ int g_schedA[NWARP][10], g_cntA[NWARP];
__device__ int g_schedB[NWARP][12], g_cntB[NWARP];

// worst case: all 64 selected channels in br0 -> 32 pairs * 2560 floats = 81920
__device__ float g_wpack[81920 + 2048];

// ---------------------------------------------------------------------------
// Kernel 1: top-64 (stable) + pairing + LPT schedule + weight packing.
// 1024 threads, 1 block.
// 3x3 pair layout per ic (stride 40 floats): ch0 dup-pairs w0..w8 (18f)+pad2,
// ch1 dup-pairs (18f)+pad2.  br1 pair layout per ic (stride 2): (wa, wb).
// ---------------------------------------------------------------------------
__global__ void sel_k(const float* __restrict__ cs,
                      const float* __restrict__ w_main,
                      const float* __restrict__ w_1x1,
                      const float* __restrict__ w32) {
    __shared__ int s_src[64];
    __shared__ int s_kind[MAXIT], s_c0[MAXIT], s_c1[MAXIT], s_off[MAXIT];
    __shared__ int s_nit;
    __shared__ int sh_l[4][64], sh_n[4], sh_cc[64];
    __shared__ int sh_load[NWARP], sh_cnt[NWARP];

    const int tid = threadIdx.x;

    if (tid < 128) {
        int j = tid;
        float key = __ldg(cs + j);
        int rank = 0;
#pragma unroll 16
        for (int i = 0; i < 128; i++) {
            float vi = __ldg(cs + i);
            rank += (vi > key || (vi == key && i < j)) ? 1 : 0;
        }
        if (rank < 64) {
            s_src[rank]   = j;
            g_scale[rank] = 1.0f / (1.0f + expf(-key));
        }
    }
    __syncthreads();

    if (tid == 0) {
        int n3 = 0;
        sh_n[0] = sh_n[1] = sh_n[2] = sh_n[3] = 0;
        for (int s = 0; s < 64; s++) {
            int src = s_src[s];
            int br = src >> 5, c = src & 31;
            sh_cc[s] = c;
            g_slot[s] = 0;
            if (br == 3) { g_slot[s] = n3; g_list3[n3++] = c; }
            sh_l[br][sh_n[br]++] = s;
        }
        int p3 = (n3 + 7) & ~7;
        for (int i = n3; i < p3; i++) g_list3[i] = n3 ? g_list3[0] : 0;
        int ng3 = p3 >> 3;

        int nit = 0;
        if (sh_n[2] > 0)
            for (int g = 0; g < 4; g++) {
                s_kind[nit] = 4; g_it_kind[nit] = 4; g_it_a[nit] = g; nit++;
            }
        if (n3 > 0)
            for (int g = 0; g < ng3; g++) {
                s_kind[nit] = 5; g_it_kind[nit] = 5; g_it_a[nit] = g; nit++;
            }

        int wo = 0;
        const int strides[3] = {2560, 128, 1280};   // br0, br1, br2
        for (int br = 0; br < 3; br++) {
            for (int i = 0; i < sh_n[br]; i += 2) {
                int s0 = sh_l[br][i];
                int s1 = (i + 1 < sh_n[br]) ? sh_l[br][i + 1] : s0;
                s_kind[nit] = br;  g_it_kind[nit] = br;
                g_it_a[nit] = s0;  g_it_b[nit] = s1;
                s_c0[nit] = sh_cc[s0]; s_c1[nit] = sh_cc[s1];
                g_it_c0[nit] = sh_cc[s0]; g_it_c1[nit] = sh_cc[s1];
                s_off[nit] = wo;   g_it_off[nit] = wo;
                wo += strides[br];
                nit++;
            }
        }
        for (int i = 0; i < sh_n[3]; i++) {
            s_kind[nit] = 3; g_it_kind[nit] = 3; g_it_a[nit] = sh_l[3][i]; nit++;
        }
        s_nit = nit;

        // ---- LPT schedule A (br0, prep, br1) ----
        const int costk[6] = {6900, 1700, 3500, 150, 5600, 5600};
        for (int w = 0; w < NWARP; w++) { sh_load[w] = 0; sh_cnt[w] = 0; }
        const int orderA[3] = {0, 4, 1};
        for (int oi = 0; oi < 3; oi++) {
            int kk = orderA[oi];
            for (int i = 0; i < nit; i++) {
                int kd = s_kind[i];
                bool match = (kk == 4) ? (kd == 4 || kd == 5) : (kd == kk);
                if (!match) continue;
                int wm = 0;
                for (int w = 1; w < NWARP; w++) if (sh_load[w] < sh_load[wm]) wm = w;
                if (sh_cnt[wm] < 10) {
                    g_schedA[wm][sh_cnt[wm]++] = i;
                    sh_load[wm] += costk[kd];
                }
            }
        }
        for (int w = 0; w < NWARP; w++) g_cntA[w] = sh_cnt[w];
        // ---- LPT schedule B (br2, avg) ----
        for (int w = 0; w < NWARP; w++) { sh_load[w] = 0; sh_cnt[w] = 0; }
        const int orderB[2] = {2, 3};
        for (int oi = 0; oi < 2; oi++) {
            int kk = orderB[oi];
            for (int i = 0; i < nit; i++) {
                if (s_kind[i] != kk) continue;
                int wm = 0;
                for (int w = 1; w < NWARP; w++) if (sh_load[w] < sh_load[wm]) wm = w;
                if (sh_cnt[wm] < 12) {
                    g_schedB[wm][sh_cnt[wm]++] = i;
                    sh_load[wm] += costk[kk];
                }
            }
        }
        for (int w = 0; w < NWARP; w++) g_cntB[w] = sh_cnt[w];
    }
    __syncthreads();

    // ---- parallel weight packing ----
    const int nit = s_nit;
    for (int it = 0; it < nit; it++) {
        int kind = s_kind[it];
        if (kind >= 3) continue;
        int c0 = s_c0[it], c1 = s_c1[it], off = s_off[it];
        if (kind == 1) {
            if (tid < 64) {
                g_wpack[off + 2 * tid]     = __ldg(w_1x1 + c0 * 64 + tid);
                g_wpack[off + 2 * tid + 1] = __ldg(w_1x1 + c1 * 64 + tid);
            }
            continue;
        }
        int CH = (kind == 0) ? CIN : MID;
        const float* src = (kind == 0) ? w_main : w32;
        for (int e = tid; e < CH * 9; e += 1024) {
            int ic = e / 9, r = e - ic * 9;
            float v0 = __ldg(src + c0 * CH * 9 + e);
            float v1 = __ldg(src + c1 * CH * 9 + e);
            int base = off + ic * 40;
            g_wpack[base + 2 * r]          = v0;
            g_wpack[base + 2 * r + 1]      = v0;
            g_wpack[base + 20 + 2 * r]     = v1;
            g_wpack[base + 20 + 2 * r + 1] = v1;
        }
    }
}

// ---------------------------------------------------------------------------
// smem layout
// ---------------------------------------------------------------------------
#define OFF_XS   0
#define OFF_T1S  (OFF_XS  + CIN*PP)
#define OFF_TAS  (OFF_T1S + MID*PP)
#define SMEM_FLOATS (OFF_TAS + MID*PP)     // 41472 floats
#define SMEM_BYTES  (SMEM_FLOATS * 4)      // 165888

extern __shared__ float smem[];

// ---------------------------------------------------------------------------
// 3x3 conv pair: half-warp per channel, lane strip = 8 rows x 2 cols (f32x2)
// ---------------------------------------------------------------------------
__device__ __forceinline__ void conv3x3_pairpx(
    int s0, int s1, int c0, int c1, int off,
    const float* __restrict__ srcp, int CH, const float* __restrict__ bnp,
    float* outb, int h0, int w0, int lane)
{
    const int ch  = lane >> 4;
    const int sub = lane & 15;
    const int cp  = (sub & 7) * 2;        // col base in tile
    const int r0  = (sub >> 3) * 8;       // row base in tile
    const int s   = ch ? s1 : s0;
    const int c   = ch ? c1 : c0;

    ull acc[8];
#pragma unroll
    for (int k = 0; k < 8; k++) acc[k] = 0ull;

    const float* wfp = g_wpack + off + ch * 20;   // per-ic stride 40 floats
    ulonglong2 q0 = *(const ulonglong2*)(wfp);
    ulonglong2 q1 = *(const ulonglong2*)(wfp + 4);
    ulonglong2 q2 = *(const ulonglong2*)(wfp + 8);
    ulonglong2 q3 = *(const ulonglong2*)(wfp + 12);
    ull        q4 = *(const ull*)(wfp + 16);

#pragma unroll 2
    for (int ic = 0; ic < CH; ic++) {
        const float* wnp = wfp + (ic + 1) * 40;   // prefetch (tail pad safe)
        ulonglong2 n0 = *(const ulonglong2*)(wnp);
        ulonglong2 n1 = *(const ulonglong2*)(wnp + 4);
        ulonglong2 n2 = *(const ulonglong2*)(wnp + 8);
        ulonglong2 n3 = *(const ulonglong2*)(wnp + 12);
        ull        n4 = *(const ull*)(wnp + 16);

        ull w0d = q0.x, w1d = q0.y, w2d = q1.x, w3d = q1.y, w4d = q2.x,
            w5d = q2.y, w6d = q3.x, w7d = q3.y, w8d = q4;

        const float* xc = srcp + ic * PP + r0 * PS + cp;
#pragma unroll
        for (int j = 0; j < 10; j++) {
            ull d0 = *(const ull*)(xc + j * PS);       // cols cp, cp+1
            ull d2 = *(const ull*)(xc + j * PS + 2);   // cols cp+2, cp+3
            ull d1 = mid2(d0, d2);                     // cols cp+1, cp+2
            if (j < 8)            { FMA2(acc[j],     d0, w0d); FMA2(acc[j],     d1, w1d); FMA2(acc[j],     d2, w2d); }
            if (j >= 1 && j < 9)  { FMA2(acc[j - 1], d0, w3d); FMA2(acc[j - 1], d1, w4d); FMA2(acc[j - 1], d2, w5d); }
            if (j >= 2)           { FMA2(acc[j - 2], d0, w6d); FMA2(acc[j - 2], d1, w7d); FMA2(acc[j - 2], d2, w8d); }
        }
        q0 = n0; q1 = n1; q2 = n2; q3 = n3; q4 = n4;
    }

    float g  = __ldg(bnp + c),      be = __ldg(bnp + 32 + c);
    float m  = __ldg(bnp + 64 + c), v  = __ldg(bnp + 96 + c);
    float iv = g * rsqrtf(v + BN_EPS);
    float bias = be - m * iv;
    float sc = g_scale[s];

    float* op = outb + ((size_t)s * HH + (h0 + r0)) * WW + (w0 + cp);
#pragma unroll
    for (int k = 0; k < 8; k++) {
        float a0, a1; upk(acc[k], a0, a1);
        float2 o;
        o.x = (a0 * iv + bias) * sc;
        o.y = (a1 * iv + bias) * sc;
        *(float2*)(op + k * WW) = o;
    }
}

// ---------------------------------------------------------------------------
__device__ __forceinline__ void run_item(
    int idx, int lane,
    float* xs, float* t1s, float* tas,
    const float* __restrict__ w31,    const float* __restrict__ bn31,
    const float* __restrict__ wavg,   const float* __restrict__ bnavg1,
    const float* __restrict__ bn_main,const float* __restrict__ bn_1x1,
    const float* __restrict__ bn32,   const float* __restrict__ bnavg2,
    float* outb, int h0, int w0)
{
    const int kind = g_it_kind[idx];

    if (kind == 0) {
        conv3x3_pairpx(g_it_a[idx], g_it_b[idx], g_it_c0[idx], g_it_c1[idx], g_it_off[idx],
                       xs, CIN, bn_main, outb, h0, w0, lane);
        return;
    }
    if (kind == 2) {
        conv3x3_pairpx(g_it_a[idx], g_it_b[idx], g_it_c0[idx], g_it_c1[idx], g_it_off[idx],
                       t1s, MID, bn32, outb, h0, w0, lane);
        return;
    }
    if (kind == 1) {
        // paired 1x1 (channel pair in f32x2 lanes)
        const int s0 = g_it_a[idx], s1 = g_it_b[idx];
        const int c0 = g_it_c0[idx], c1 = g_it_c1[idx];
        const ull* wp = (const ull*)(g_wpack + g_it_off[idx]);
        const int c16 = lane & 15, r0 = (lane >> 4) * 8;
        ull acc[8];
#pragma unroll
        for (int k = 0; k < 8; k++) acc[k] = 0ull;
        const int pcx = (r0 + 1) * PS + (c16 + 1);
#pragma unroll 4
        for (int ic = 0; ic < CIN; ic++) {
            ull wv = __ldg(wp + ic);
            const float* xc = xs + ic * PP + pcx;
#pragma unroll
            for (int k = 0; k < 8; k++) {
                ull xd = pk2(xc[k * PS]);
                FMA2(acc[k], xd, wv);
            }
        }
        float g0  = __ldg(bn_1x1 + c0),      be0 = __ldg(bn_1x1 + 32 + c0);
        float m0  = __ldg(bn_1x1 + 64 + c0), v0  = __ldg(bn_1x1 + 96 + c0);
        float g1  = __ldg(bn_1x1 + c1),      be1 = __ldg(bn_1x1 + 32 + c1);
        float m1  = __ldg(bn_1x1 + 64 + c1), v1  = __ldg(bn_1x1 + 96 + c1);
        float iv0 = g0 * rsqrtf(v0 + BN_EPS), b0 = be0 - m0 * iv0;
        float iv1 = g1 * rsqrtf(v1 + BN_EPS), b1 = be1 - m1 * iv1;
        float sc0 = g_scale[s0], sc1 = g_scale[s1];
        float* op0 = outb + ((size_t)s0 * HH + (h0 + r0)) * WW + (w0 + c16);
        float* op1 = outb + ((size_t)s1 * HH + (h0 + r0)) * WW + (w0 + c16);
#pragma unroll
        for (int k = 0; k < 8; k++) {
            float a0, a1; upk(acc[k], a0, a1);
            op0[k * WW] = (a0 * iv0 + b0) * sc0;
            op1[k * WW] = (a1 * iv1 + b1) * sc1;
        }
        return;
    }
    if (kind == 3) {
        const int s = g_it_a[idx];
        const int c16 = lane & 15, r0 = (lane >> 4) * 8;
        const int slot = g_slot[s];
        const float* tc = tas + slot * PP + r0 * PS + c16;
        float rs[10];
#pragma unroll
        for (int j = 0; j < 10; j++)
            rs[j] = tc[j * PS] + tc[j * PS + 1] + tc[j * PS + 2];
        int c = g_list3[slot];
        float g  = __ldg(bnavg2 + c),      be = __ldg(bnavg2 + 32 + c);
        float m  = __ldg(bnavg2 + 64 + c), v  = __ldg(bnavg2 + 96 + c);
        float iv = g * rsqrtf(v + BN_EPS);
        float bias = be - m * iv;
        float sc = g_scale[s];
        float* op = outb + ((size_t)s * HH + (h0 + r0)) * WW + (w0 + c16);
#pragma unroll
        for (int k = 0; k < 8; k++) {
            float a = (rs[k] + rs[k + 1] + rs[k + 2]) * (1.0f / 9.0f);
            op[k * WW] = (a * iv + bias) * sc;
        }
        return;
    }

    // ---------- prep item (kind 4 = t1 group, kind 5 = ta group) ----------
    {
        bool isT1 = (kind == 4);
        int gi = g_it_a[idx];
        const float* wg  = isT1 ? w31 : wavg;
        const float* bnp = isT1 ? bn31 : bnavg1;
        float* dst = isT1 ? t1s : tas;

        int ch[8];
#pragma unroll
        for (int jj = 0; jj < 8; jj++)
            ch[jj] = isT1 ? (gi * 8 + jj) : g_list3[gi * 8 + jj];

        float inv8[8], bias8[8];
#pragma unroll
        for (int jj = 0; jj < 8; jj++) {
            int c = ch[jj];
            float g = __ldg(bnp + c),      be = __ldg(bnp + 32 + c);
            float m = __ldg(bnp + 64 + c), v  = __ldg(bnp + 96 + c);
            float iv = g * rsqrtf(v + BN_EPS);
            inv8[jj] = iv; bias8[jj] = be - m * iv;
        }

        for (int pass = 0; pass < 3; pass++) {
            int p0 = pass * 128 + (threadIdx.x & 31) * 4;
            if (p0 >= PP) continue;
            bool inq[4];
            bool allin = true;
#pragma unroll
            for (int q = 0; q < 4; q++) {
                int p = p0 + q;
                int py = p / PS, px = p - py * PS;
                inq[q] = ((unsigned)(h0 + py - 1) < HH) && ((unsigned)(w0 + px - 1) < WW);
                allin = allin && inq[q];
            }
#pragma unroll
            for (int half = 0; half < 2; half++) {
                ull acc2[4][2];
#pragma unroll
                for (int a = 0; a < 4; a++) { acc2[a][0] = 0ull; acc2[a][1] = 0ull; }

#pragma unroll 4
                for (int icg = 0; icg < CIN / 4; icg++) {
                    ulonglong2 xv0 = *(const ulonglong2*)(xs + (icg * 4 + 0) * PP + p0);
                    ulonglong2 xv1 = *(const ulonglong2*)(xs + (icg * 4 + 1) * PP + p0);
                    ulonglong2 xv2 = *(const ulonglong2*)(xs + (icg * 4 + 2) * PP + p0);
                    ulonglong2 xv3 = *(const ulonglong2*)(xs + (icg * 4 + 3) * PP + p0);
#pragma unroll
                    for (int jj = 0; jj < 4; jj++) {
                        float4 wq = __ldg((const float4*)(wg + ch[half * 4 + jj] * CIN + icg * 4));
                        ull wd0 = pk2(wq.x), wd1 = pk2(wq.y), wd2 = pk2(wq.z), wd3 = pk2(wq.w);
                        FMA2(acc2[jj][0], xv0.x, wd0); FMA2(acc2[jj][1], xv0.y, wd0);
                        FMA2(acc2[jj][0], xv1.x, wd1); FMA2(acc2[jj][1], xv1.y, wd1);
                        FMA2(acc2[jj][0], xv2.x, wd2); FMA2(acc2[jj][1], xv2.y, wd2);
                        FMA2(acc2[jj][0], xv3.x, wd3); FMA2(acc2[jj][1], xv3.y, wd3);
                    }
                }
#pragma unroll
                for (int jj = 0; jj < 4; jj++) {
                    int j8 = half * 4 + jj;
                    int slot = gi * 8 + j8;
                    ull ivd = pk2(inv8[j8]);
                    ull t0 = pk2(bias8[j8]);
                    ull t1 = t0;
                    FMA2(t0, acc2[jj][0], ivd);
                    FMA2(t1, acc2[jj][1], ivd);
                    float* dp = dst + slot * PP + p0;
                    if (allin) {
                        *(ull*)(dp)     = t0;
                        *(ull*)(dp + 2) = t1;
                    } else {
                        float a0, a1, a2, a3;
                        upk(t0, a0, a1); upk(t1, a2, a3);
                        dp[0] = inq[0] ? a0 : 0.0f;
                        dp[1] = inq[1] ? a1 : 0.0f;
                        dp[2] = inq[2] ? a2 : 0.0f;
                        dp[3] = inq[3] ? a3 : 0.0f;
                    }
                }
            }
        }
    }
}

// ---------------------------------------------------------------------------
__global__ __launch_bounds__(512, 1)
void fused_k(const float* __restrict__ x,
             const float* __restrict__ bn_main,
             const float* __restrict__ bn_1x1,
             const float* __restrict__ w31,    const float* __restrict__ bn31,
             const float* __restrict__ bn32,
             const float* __restrict__ wavg,   const float* __restrict__ bnavg1,
             const float* __restrict__ bnavg2,
             float* __restrict__ out)
{
    float* xs  = smem + OFF_XS;
    float* t1s = smem + OFF_T1S;
    float* tas = smem + OFF_TAS;

    const int tid  = threadIdx.x;
    const int warp = tid >> 5, lane = tid & 31;
    const int b  = blockIdx.z;
    const int h0 = blockIdx.y * TS;
    const int w0 = blockIdx.x * TS;

    const float* xb = x + (size_t)b * CIN * HH * WW;
    for (int i = tid; i < CIN * PP; i += 512) {
        int ic = i / PP;
        int p  = i - ic * PP;
        int py = p / PS, px = p - py * PS;
        int gh = h0 + py - 1, gw = w0 + px - 1;
        float v = 0.0f;
        if ((unsigned)gh < HH && (unsigned)gw < WW)
            v = xb[(ic * HH + gh) * WW + gw];
        xs[i] = v;
    }
    __syncthreads();

    float* outb = out + (size_t)b * 64 * HH * WW;

    int ca = g_cntA[warp];
    for (int k = 0; k < ca; k++)
        run_item(g_schedA[warp][k], lane, xs, t1s, tas,
                 w31, bn31, wavg, bnavg1, bn_main, bn_1x1, bn32, bnavg2,
                 outb, h0, w0);
    __syncthreads();

    int cb = g_cntB[warp];
    for (int k = 0; k < cb; k++)
        run_item(g_schedB[warp][k], lane, xs, t1s, tas,
                 w31, bn31, wavg, bnavg1, bn_main, bn_1x1, bn32, bnavg2,
                 outb, h0, w0);
}

// ---------------------------------------------------------------------------
extern "C" void kernel_launch(void* const* d_in, const int* in_sizes, int n_in,
                              void* d_out, int out_size) {
    const float* x       = (const float*)d_in[0];
    const float* w_main  = (const float*)d_in[1];
    const float* bn_main = (const float*)d_in[2];
    const float* w_1x1   = (const float*)d_in[3];
    const float* bn_1x1  = (const float*)d_in[4];
    const float* w31     = (const float*)d_in[5];
    const float* bn31    = (const float*)d_in[6];
    const float* w32     = (const float*)d_in[7];
    const float* bn32    = (const float*)d_in[8];
    const float* wavg    = (const float*)d_in[9];
    const float* bnavg1  = (const float*)d_in[10];
    const float* bnavg2  = (const float*)d_in[11];
    const float* c_score = (const float*)d_in[12];
    float* out = (float*)d_out;

    static int cfg_done = 0;
    if (!cfg_done) {
        cudaFuncSetAttribute(fused_k, cudaFuncAttributeMaxDynamicSharedMemorySize, SMEM_BYTES);
        cfg_done = 1;
    }

    sel_k<<<1, 1024>>>(c_score, w_main, w_1x1, w32);

    dim3 grid(WW / TS, HH / TS, BSZ);
    fused_k<<<grid, 512, SMEM_BYTES>>>(x, bn_main, bn_1x1,
                                       w31, bn31, bn32,
                                       wavg, bnavg1, bnavg2, out);
}